// round 7
// baseline (speedup 1.0000x reference)
#include <cuda_runtime.h>

#define B_   128
#define NT   64
#define WIN  200
#define EMB  128

typedef unsigned long long ull;
#define NEG_INF (__int_as_float(0xff800000))

__device__ __forceinline__ ull fma2v(ull a, ull b, ull c) {
    ull d; asm("fma.rn.f32x2 %0, %1, %2, %3;" : "=l"(d) : "l"(a), "l"(b), "l"(c)); return d;
}
__device__ __forceinline__ ull pack2(float x, float y) {
    ull d; asm("mov.b64 %0, {%1, %2};" : "=l"(d) : "f"(x), "f"(y)); return d;
}
__device__ __forceinline__ float2 unpack2(ull a) {
    float2 r; asm("mov.b64 {%0, %1}, %2;" : "=f"(r.x), "=f"(r.y) : "l"(a)); return r;
}
__device__ __forceinline__ void relu_dot2(ull& acc, ull hp, ull hq, ull hw) {
    asm("{\n\t"
        ".reg .b64 s;\n\t"
        ".reg .f32 lo, hi;\n\t"
        "add.rn.f32x2 s, %1, %2;\n\t"
        "mov.b64 {lo, hi}, s;\n\t"
        "max.f32 lo, lo, 0f00000000;\n\t"
        "max.f32 hi, hi, 0f00000000;\n\t"
        "mov.b64 s, {lo, hi};\n\t"
        "fma.rn.f32x2 %0, s, %3, %0;\n\t"
        "}" : "+l"(acc) : "l"(hp), "l"(hq), "l"(hw));
}

// global scratch (L2-resident)
__device__ float HQg[B_ * WIN * EMB];   // [b*200+w][128]
__device__ float HPg[B_ * NT * EMB];    // [b*64+t][128]

// ===================== K1: projections =====================
// grid = 400 (hq rows) + 128 (hp rows); block 256.
// Each block: 64 gathered rows x 128 n.
#define K1_HQ_BLOCKS 400
#define K1_BLOCKS    528

#define K1_X    0               /* [64][132] */
#define K1_WC   8448            /* [32][130] */
#define K1_ITM  12608           /* 64 ints   */
#define K1_FLOATS 12680
#define K1_BYTES (K1_FLOATS * 4)

__global__ void __launch_bounds__(256)
proj_kernel(const float* __restrict__ tvecs, const float* __restrict__ cvecs,
            const float* __restrict__ W_w, const float* __restrict__ W_b,
            const int* __restrict__ titems, const int* __restrict__ citems)
{
    extern __shared__ float sm[];
    float* X  = sm + K1_X;
    float* Wc = sm + K1_WC;
    int*  itm = (int*)(sm + K1_ITM);
    const int tid = threadIdx.x;

    const bool is_hq = blockIdx.x < K1_HQ_BLOCKS;
    const int rbase = (is_hq ? blockIdx.x : (blockIdx.x - K1_HQ_BLOCKS)) * 64;
    const float* vecs = is_hq ? cvecs : tvecs;
    const int* items  = is_hq ? citems : titems;
    const int rowsper = is_hq ? WIN : NT;
    const int wcol    = is_hq ? EMB : 0;
    float* outg       = is_hq ? HQg : HPg;

    if (tid < 64) {
        int r = rbase + tid;
        itm[tid] = items[(r / rowsper) * rowsper + (r % rowsper)];
    }
    __syncthreads();

    // gather X rows [64][128] (pitch 132)
    for (int i = tid; i < 64 * 32; i += 256) {
        int row = i >> 5, c = i & 31;
        *(float4*)(X + row * 132 + c * 4) =
            *(const float4*)(vecs + (size_t)itm[row] * EMB + c * 4);
    }

    const int rg = tid & 15;        // rows rg, rg+16, rg+32, rg+48
    const int ng = tid >> 4;        // n = ng*8 .. ng*8+7
    ull acc[4][4];
#pragma unroll
    for (int i = 0; i < 4; i++)
#pragma unroll
        for (int j = 0; j < 4; j++) acc[i][j] = 0ull;

    for (int ec = 0; ec < 4; ++ec) {
        __syncthreads();            // X ready / prev compute done
        for (int i = tid; i < 4096; i += 256) {
            int n = i >> 5, e = i & 31;
            Wc[e * 130 + n] = W_w[n * 256 + wcol + ec * 32 + e];
        }
        __syncthreads();
#pragma unroll
        for (int e4 = 0; e4 < 8; ++e4) {
            float4 xv[4];
#pragma unroll
            for (int i = 0; i < 4; i++)
                xv[i] = *(const float4*)(X + (rg + 16 * i) * 132 + ec * 32 + e4 * 4);
#pragma unroll
            for (int s = 0; s < 4; ++s) {
                int e = e4 * 4 + s;
                ull w2[4];
#pragma unroll
                for (int j = 0; j < 4; j++)
                    w2[j] = *(const ull*)(Wc + e * 130 + ng * 8 + 2 * j);
#pragma unroll
                for (int i = 0; i < 4; i++) {
                    float x = (s == 0) ? xv[i].x : (s == 1) ? xv[i].y
                             : (s == 2) ? xv[i].z : xv[i].w;
                    ull xd = pack2(x, x);
#pragma unroll
                    for (int j = 0; j < 4; j++) acc[i][j] = fma2v(xd, w2[j], acc[i][j]);
                }
            }
        }
    }
    // epilogue: +Wb for hq role, store
#pragma unroll
    for (int i = 0; i < 4; i++) {
        int r = rbase + rg + 16 * i;
#pragma unroll
        for (int j = 0; j < 4; j++) {
            int n = ng * 8 + 2 * j;
            float2 a = unpack2(acc[i][j]);
            if (is_hq) { a.x += __ldg(W_b + n); a.y += __ldg(W_b + n + 1); }
            *(float2*)(outg + (size_t)r * EMB + n) = a;
        }
    }
}

// ===================== K2: relu-dot + softmax + AV =====================
// grid 512 = 128 batches x 4 t-tiles(16 t); block 256 (8 warps, 2 t per warp)
#define K2_HQ    0              /* [32][132] chunk; reused for k */
#define K2_HP    4224           /* [16][132] */
#define K2_HW    6336           /* [128]     */
#define K2_ATT   6464           /* [16][224] */
#define K2_MADD  10048          /* [200]     */
#define K2_CI    10248          /* 200 ints  */
#define K2_MISC  10448          /* [0]=rnorm [1]=flag */
#define K2_FLOATS 10456
#define K2_BYTES (K2_FLOATS * 4)

__global__ void __launch_bounds__(256)
att_kernel(const float* __restrict__ cvecs, const float* __restrict__ h_w,
           const int* __restrict__ citems, const unsigned char* __restrict__ mask,
           float* __restrict__ out)
{
    extern __shared__ float sm[];
    float* SHQ  = sm + K2_HQ;
    float* SHP  = sm + K2_HP;
    float* SHW  = sm + K2_HW;
    float* ATT  = sm + K2_ATT;
    float* MADD = sm + K2_MADD;
    int*   CI   = (int*)(sm + K2_CI);
    const int tid = threadIdx.x;
    const int b  = blockIdx.x >> 2;
    const int t0 = (blockIdx.x & 3) * 16;
    const int warp = tid >> 5, lane = tid & 31;

    // mask layout detect + stage madd/ci/hw/hp
    if (tid == 0) ((int*)sm)[K2_MISC + 1] = 0;
    __syncthreads();
    if (tid < 200) {
        unsigned w32 = ((const unsigned*)mask)[tid];
        if (w32 > 1u) ((int*)sm)[K2_MISC + 1] = 1;   // benign race
    }
    __syncthreads();
    {
        const bool bytes_layout = ((int*)sm)[K2_MISC + 1] != 0;
        if (tid < 200) {
            int mv = bytes_layout ? (int)mask[b * WIN + tid]
                                  : ((const int*)mask)[b * WIN + tid];
            MADD[tid] = mv ? NEG_INF : 0.0f;
            CI[tid] = citems[b * WIN + tid];
        }
        if (tid < 128) SHW[tid] = h_w[tid];
    }
    for (int i = tid; i < 16 * 32; i += 256) {
        int t = i >> 5, c = i & 31;
        *(float4*)(SHP + t * 132 + c * 4) =
            *(const float4*)(HPg + ((size_t)(b * NT + t0 + t)) * EMB + c * 4);
    }
    __syncthreads();
    if (tid < 32) {  // rnorm
        float c = 0.0f;
        for (int w = tid; w < WIN; w += 32) c += (MADD[w] < 0.0f) ? 1.0f : 0.0f;
#pragma unroll
        for (int o = 16; o; o >>= 1) c += __shfl_xor_sync(0xffffffffu, c, o);
        if (tid == 0) sm[K2_MISC] = 1.0f / sqrtf(1000.0f - c);
    }

    // ---- att: per chunk of 32 w ----
    for (int wc = 0; wc < 7; ++wc) {
        const int wbase = wc * 32;
        __syncthreads();
        for (int i = tid; i < 32 * 32; i += 256) {
            int wr = i >> 5, c = i & 31;
            float4 v = make_float4(0.f, 0.f, 0.f, 0.f);
            if (wbase + wr < WIN)
                v = *(const float4*)(HQg + ((size_t)(b * WIN + wbase + wr)) * EMB + c * 4);
            *(float4*)(SHQ + wr * 132 + c * 4) = v;
        }
        __syncthreads();
        ull a0 = 0ull, a1 = 0ull;
#pragma unroll 8
        for (int ns = 0; ns < 32; ++ns) {
            ulonglong2 hq = *(const ulonglong2*)(SHQ + lane * 132 + ns * 4);
            ulonglong2 p0 = *(const ulonglong2*)(SHP + (2 * warp) * 132 + ns * 4);
            ulonglong2 p1 = *(const ulonglong2*)(SHP + (2 * warp + 1) * 132 + ns * 4);
            ulonglong2 hw = *(const ulonglong2*)(SHW + ns * 4);
            relu_dot2(a0, p0.x, hq.x, hw.x); relu_dot2(a0, p0.y, hq.y, hw.y);
            relu_dot2(a1, p1.x, hq.x, hw.x); relu_dot2(a1, p1.y, hq.y, hw.y);
        }
        if (wbase + lane < WIN) {
            float2 A = unpack2(a0), Bv = unpack2(a1);
            ATT[(2 * warp) * 224 + wbase + lane] = A.x + A.y;
            ATT[(2 * warp + 1) * 224 + wbase + lane] = Bv.x + Bv.y;
        }
    }
    __syncthreads();

    // ---- softmax over w per t (2 t per warp) ----
    for (int t = warp; t < 16; t += 8) {
        float v[7], p[7];
        float m = NEG_INF;
#pragma unroll
        for (int k = 0; k < 7; k++) {
            int w = lane + 32 * k;
            v[k] = (w < WIN) ? (ATT[t * 224 + w] + MADD[w]) : NEG_INF;
            m = fmaxf(m, v[k]);
        }
#pragma unroll
        for (int o = 16; o; o >>= 1) m = fmaxf(m, __shfl_xor_sync(0xffffffffu, m, o));
        float s = 0.0f;
#pragma unroll
        for (int k = 0; k < 7; k++) { p[k] = __expf(v[k] - m); s += p[k]; }
#pragma unroll
        for (int o = 16; o; o >>= 1) s += __shfl_xor_sync(0xffffffffu, s, o);
        float inv = 1.0f / s;
#pragma unroll
        for (int k = 0; k < 7; k++) {
            int w = lane + 32 * k;
            if (w < WIN) ATT[t * 224 + w] = p[k] * inv;
        }
    }
    // zero ATT pad (w 200..223)
    for (int i = tid; i < 16 * 24; i += 256)
        ATT[(i / 24) * 224 + 200 + (i % 24)] = 0.0f;

    // ---- AV: out[t][e] = rn * sum_w att*k ----
    ull o00 = 0ull, o01 = 0ull, o10 = 0ull, o11 = 0ull;
    for (int wc = 0; wc < 7; ++wc) {
        const int wbase = wc * 32;
        __syncthreads();
        for (int i = tid; i < 32 * 32; i += 256) {
            int wr = i >> 5, c = i & 31;
            float4 v = make_float4(0.f, 0.f, 0.f, 0.f);
            if (wbase + wr < WIN)
                v = *(const float4*)(cvecs + (size_t)CI[wbase + wr] * EMB + c * 4);
            *(float4*)(SHQ + wr * 132 + c * 4) = v;
        }
        __syncthreads();
#pragma unroll 4
        for (int wr = 0; wr < 32; ++wr) {
            float x0 = ATT[(2 * warp) * 224 + wbase + wr];
            float x1 = ATT[(2 * warp + 1) * 224 + wbase + wr];
            ulonglong2 kv = *(const ulonglong2*)(SHQ + wr * 132 + lane * 4);
            ull d0 = pack2(x0, x0), d1 = pack2(x1, x1);
            o00 = fma2v(d0, kv.x, o00); o01 = fma2v(d0, kv.y, o01);
            o10 = fma2v(d1, kv.x, o10); o11 = fma2v(d1, kv.y, o11);
        }
    }
    {
        const float rn = sm[K2_MISC];
        float2 A = unpack2(o00), Bv = unpack2(o01), C = unpack2(o10), D = unpack2(o11);
        float4 r0 = make_float4(A.x * rn, A.y * rn, Bv.x * rn, Bv.y * rn);
        float4 r1 = make_float4(C.x * rn, C.y * rn, D.x * rn, D.y * rn);
        size_t row0 = (size_t)(b * NT + t0 + 2 * warp) * EMB + lane * 4;
        *(float4*)(out + row0) = r0;
        *(float4*)(out + row0 + EMB) = r1;
    }
}

extern "C" void kernel_launch(void* const* d_in, const int* in_sizes, int n_in,
                              void* d_out, int out_size)
{
    const float* tvecs = (const float*)d_in[0];
    const float* cvecs = (const float*)d_in[1];
    const float* W_w   = (const float*)d_in[2];
    const float* W_b   = (const float*)d_in[3];
    const float* h_w   = (const float*)d_in[4];
    const int*   ti    = (const int*)d_in[6];
    const int*   ci    = (const int*)d_in[7];
    const unsigned char* mask = (const unsigned char*)d_in[8];

    cudaFuncSetAttribute(proj_kernel, cudaFuncAttributeMaxDynamicSharedMemorySize, K1_BYTES);
    cudaFuncSetAttribute(att_kernel,  cudaFuncAttributeMaxDynamicSharedMemorySize, K2_BYTES);
    proj_kernel<<<K1_BLOCKS, 256, K1_BYTES>>>(tvecs, cvecs, W_w, W_b, ti, ci);
    att_kernel<<<B_ * 4, 256, K2_BYTES>>>(cvecs, h_w, ci, mask, (float*)d_out);
}

// round 10
// speedup vs baseline: 1.1930x; 1.1930x over previous
#include <cuda_runtime.h>

#define B_   128
#define NT   64
#define WIN  200
#define EMB  128

typedef unsigned long long ull;
#define NEG_INF (__int_as_float(0xff800000))

__device__ __forceinline__ ull fma2v(ull a, ull b, ull c) {
    ull d; asm("fma.rn.f32x2 %0, %1, %2, %3;" : "=l"(d) : "l"(a), "l"(b), "l"(c)); return d;
}
__device__ __forceinline__ ull pack2(float x, float y) {
    ull d; asm("mov.b64 %0, {%1, %2};" : "=l"(d) : "f"(x), "f"(y)); return d;
}
__device__ __forceinline__ float2 unpack2(ull a) {
    float2 r; asm("mov.b64 {%0, %1}, %2;" : "=f"(r.x), "=f"(r.y) : "l"(a)); return r;
}
__device__ __forceinline__ void relu_dot2(ull& acc, ull hp, ull hq, ull hw) {
    asm("{\n\t"
        ".reg .b64 s;\n\t"
        ".reg .f32 lo, hi;\n\t"
        "add.rn.f32x2 s, %1, %2;\n\t"
        "mov.b64 {lo, hi}, s;\n\t"
        "max.f32 lo, lo, 0f00000000;\n\t"
        "max.f32 hi, hi, 0f00000000;\n\t"
        "mov.b64 s, {lo, hi};\n\t"
        "fma.rn.f32x2 %0, s, %3, %0;\n\t"
        "}" : "+l"(acc) : "l"(hp), "l"(hq), "l"(hw));
}

// global scratch (L2-resident)
__device__ float HQg[B_ * WIN * EMB];   // [b*200+w][128]
__device__ float HPg[B_ * NT * EMB];    // [b*64+t][128]

// ===================== K1 v2: projections, broadcast-X / conflict-free-W ====
// grid = 800 (hq, 32 rows each) + 256 (hp); block 256 = 8 warps x 4 rows.
// lane owns n in {2l, 2l+1, 64+2l, 64+2l+1}.
#define K1_HQ_BLOCKS 800
#define K1_BLOCKS    1056

#define K1_X    0               /* [32][132] */
#define K1_WC   4224            /* [32][130] */
#define K1_ITM  8384            /* 32 ints   */
#define K1_FLOATS 8416
#define K1_BYTES (K1_FLOATS * 4)

__global__ void __launch_bounds__(256)
proj_kernel(const float* __restrict__ tvecs, const float* __restrict__ cvecs,
            const float* __restrict__ W_w, const float* __restrict__ W_b,
            const int* __restrict__ titems, const int* __restrict__ citems)
{
    extern __shared__ float sm[];
    float* X  = sm + K1_X;
    float* Wc = sm + K1_WC;
    int*  itm = (int*)(sm + K1_ITM);
    const int tid = threadIdx.x;
    const int warp = tid >> 5, lane = tid & 31;

    const bool is_hq = blockIdx.x < K1_HQ_BLOCKS;
    const int rbase = (is_hq ? blockIdx.x : (blockIdx.x - K1_HQ_BLOCKS)) * 32;
    const float* vecs = is_hq ? cvecs : tvecs;
    const int* items  = is_hq ? citems : titems;
    const int rowsper = is_hq ? WIN : NT;
    const int wcol    = is_hq ? EMB : 0;
    float* outg       = is_hq ? HQg : HPg;

    if (tid < 32) {
        int r = rbase + tid;
        itm[tid] = items[(r / rowsper) * rowsper + (r % rowsper)];
    }
    __syncthreads();

    // gather X rows [32][128] (pitch 132), coalesced per row
    for (int i = tid; i < 32 * 32; i += 256) {
        int row = i >> 5, c = i & 31;
        *(float4*)(X + row * 132 + c * 4) =
            *(const float4*)(vecs + (size_t)itm[row] * EMB + c * 4);
    }

    ull acc[4][2];
#pragma unroll
    for (int r = 0; r < 4; r++) { acc[r][0] = 0ull; acc[r][1] = 0ull; }

    for (int ec = 0; ec < 4; ++ec) {
        __syncthreads();            // X ready (ec=0) / prev compute done
        for (int i = tid; i < 4096; i += 256) {
            int n = i >> 5, e = i & 31;
            Wc[e * 130 + n] = W_w[n * 256 + wcol + ec * 32 + e];
        }
        __syncthreads();
#pragma unroll
        for (int e4 = 0; e4 < 8; ++e4) {
            float4 xv[4];
#pragma unroll
            for (int r = 0; r < 4; r++)   // lane-uniform -> broadcast
                xv[r] = *(const float4*)(X + (warp * 4 + r) * 132 + ec * 32 + e4 * 4);
#pragma unroll
            for (int s = 0; s < 4; ++s) {
                int e = e4 * 4 + s;
                ull wa = *(const ull*)(Wc + e * 130 + 2 * lane);        // conflict-free
                ull wb = *(const ull*)(Wc + e * 130 + 64 + 2 * lane);   // conflict-free
#pragma unroll
                for (int r = 0; r < 4; r++) {
                    float x = (s == 0) ? xv[r].x : (s == 1) ? xv[r].y
                             : (s == 2) ? xv[r].z : xv[r].w;
                    ull xd = pack2(x, x);
                    acc[r][0] = fma2v(xd, wa, acc[r][0]);
                    acc[r][1] = fma2v(xd, wb, acc[r][1]);
                }
            }
        }
    }
    // epilogue: +Wb (hq only), coalesced float2 stores
    float2 b0 = make_float2(0.f, 0.f), b1 = b0;
    if (is_hq) {
        b0 = *(const float2*)(W_b + 2 * lane);
        b1 = *(const float2*)(W_b + 64 + 2 * lane);
    }
#pragma unroll
    for (int r = 0; r < 4; r++) {
        int rg = rbase + warp * 4 + r;
        float2 a0 = unpack2(acc[r][0]); a0.x += b0.x; a0.y += b0.y;
        float2 a1 = unpack2(acc[r][1]); a1.x += b1.x; a1.y += b1.y;
        *(float2*)(outg + (size_t)rg * EMB + 2 * lane) = a0;
        *(float2*)(outg + (size_t)rg * EMB + 64 + 2 * lane) = a1;
    }
}

// ===================== K2: relu-dot + softmax + AV (unchanged from R7) =====
// grid 512 = 128 b x 4 t-tiles(16); block 256 (8 warps)
#define K2_SHP   0
#define K2_SCR   0
#define K2_HW    8192
#define K2_ATT   8320           /* [16][224] */
#define K2_MADD  11904
#define K2_CI    12104
#define K2_MISC  12304          /* [0]=rnorm [1]=mask flag */
#define K2_FLOATS 12312
#define K2_BYTES (K2_FLOATS * 4)

__global__ void __launch_bounds__(256)
att_kernel(const float* __restrict__ cvecs, const float* __restrict__ h_w,
           const int* __restrict__ citems, const unsigned char* __restrict__ mask,
           float* __restrict__ out)
{
    extern __shared__ float sm[];
    float* SHP  = sm + K2_SHP;
    float* SHW  = sm + K2_HW;
    float* ATT  = sm + K2_ATT;
    float* MADD = sm + K2_MADD;
    int*   CI   = (int*)(sm + K2_CI);
    const int tid = threadIdx.x;
    const int b  = blockIdx.x >> 2;
    const int t0 = (blockIdx.x & 3) * 16;
    const int warp = tid >> 5, lane = tid & 31;

    if (tid == 0) ((int*)sm)[K2_MISC + 1] = 0;
    __syncthreads();
    if (tid < 200) {
        unsigned w32 = ((const unsigned*)mask)[tid];
        if (w32 > 1u) ((int*)sm)[K2_MISC + 1] = 1;   // benign race
    }
    __syncthreads();
    {
        const bool bytes_layout = ((int*)sm)[K2_MISC + 1] != 0;
        if (tid < 200) {
            int mv = bytes_layout ? (int)mask[b * WIN + tid]
                                  : ((const int*)mask)[b * WIN + tid];
            MADD[tid] = mv ? NEG_INF : 0.0f;
            CI[tid] = citems[b * WIN + tid];
        }
        if (tid < 128) SHW[tid] = h_w[tid];
    }
    for (int i = tid; i < 16 * 32; i += 256) {
        int t = i >> 5, c = i & 31;
        *(float4*)(SHP + t * 132 + c * 4) =
            *(const float4*)(HPg + ((size_t)(b * NT + t0 + t)) * EMB + c * 4);
    }
    __syncthreads();
    if (tid < 32) {  // rnorm (read at the very end, after later syncs)
        float c = 0.0f;
        for (int w = tid; w < WIN; w += 32) c += (MADD[w] < 0.0f) ? 1.0f : 0.0f;
#pragma unroll
        for (int o = 16; o; o >>= 1) c += __shfl_xor_sync(0xffffffffu, c, o);
        if (tid == 0) sm[K2_MISC] = 1.0f / sqrtf(1000.0f - c);
    }

    // ---- att: thread owns one w; hq straight from L2; hp/hw smem broadcasts ----
    {
        const int w = tid;
        const bool act = (w < WIN);
        const float* hqrow = HQg + (size_t)(b * WIN + (act ? w : 0)) * EMB;
        ull acc[16];
#pragma unroll
        for (int t = 0; t < 16; ++t) acc[t] = 0ull;
#pragma unroll 2
        for (int ns = 0; ns < 32; ++ns) {
            ulonglong2 hq = *(const ulonglong2*)(hqrow + ns * 4);
            ulonglong2 hw = *(const ulonglong2*)(SHW + ns * 4);
#pragma unroll
            for (int t = 0; t < 16; ++t) {
                ulonglong2 p = *(const ulonglong2*)(SHP + t * 132 + ns * 4);
                relu_dot2(acc[t], p.x, hq.x, hw.x);
                relu_dot2(acc[t], p.y, hq.y, hw.y);
            }
        }
        if (act) {
#pragma unroll
            for (int t = 0; t < 16; ++t) {
                float2 a = unpack2(acc[t]);
                ATT[t * 224 + w] = a.x + a.y;
            }
        }
    }
    __syncthreads();

    // ---- softmax over w per t (8 warps x 2t) ----
    for (int t = warp; t < 16; t += 8) {
        float v[7], p[7];
        float m = NEG_INF;
#pragma unroll
        for (int k = 0; k < 7; k++) {
            int w = lane + 32 * k;
            v[k] = (w < WIN) ? (ATT[t * 224 + w] + MADD[w]) : NEG_INF;
            m = fmaxf(m, v[k]);
        }
#pragma unroll
        for (int o = 16; o; o >>= 1) m = fmaxf(m, __shfl_xor_sync(0xffffffffu, m, o));
        float s = 0.0f;
#pragma unroll
        for (int k = 0; k < 7; k++) { p[k] = __expf(v[k] - m); s += p[k]; }
#pragma unroll
        for (int o = 16; o; o >>= 1) s += __shfl_xor_sync(0xffffffffu, s, o);
        float inv = 1.0f / s;
#pragma unroll
        for (int k = 0; k < 7; k++) {
            int w = lane + 32 * k;
            if (w < WIN) ATT[t * 224 + w] = p[k] * inv;
        }
    }
    __syncthreads();   // ATT final; SHP dead -> scratch reuse safe

    // ---- AV: warp = (t-half, w-quarter); kv straight from L2; partials in smem ----
    {
        const int th = warp & 1, wg = warp >> 1;
        float* SCR = sm + K2_SCR;
        ull acc[8][2];
#pragma unroll
        for (int t8 = 0; t8 < 8; ++t8) { acc[t8][0] = 0ull; acc[t8][1] = 0ull; }
#pragma unroll 2
        for (int wi = 0; wi < 50; ++wi) {
            int w = wg * 50 + wi;
            ulonglong2 kv = *(const ulonglong2*)(cvecs + (size_t)CI[w] * EMB + lane * 4);
#pragma unroll
            for (int t8 = 0; t8 < 8; ++t8) {
                float x = ATT[(th * 8 + t8) * 224 + w];   // broadcast
                ull d = pack2(x, x);
                acc[t8][0] = fma2v(d, kv.x, acc[t8][0]);
                acc[t8][1] = fma2v(d, kv.y, acc[t8][1]);
            }
        }
#pragma unroll
        for (int t8 = 0; t8 < 8; ++t8) {
            ulonglong2 v; v.x = acc[t8][0]; v.y = acc[t8][1];
            *(ulonglong2*)(SCR + (size_t)(warp * 8 + t8) * 128 + lane * 4) = v;
        }
    }
    __syncthreads();

    // ---- reduce 4 partials + scale + store ----
    {
        const float rn = sm[K2_MISC];
        for (int i = tid; i < 16 * 128; i += 256) {
            int t = i >> 7, e = i & 127;
            int th = t >> 3, t8 = t & 7;
            float s = 0.0f;
#pragma unroll
            for (int wg = 0; wg < 4; ++wg)
                s += sm[K2_SCR + (size_t)((wg * 2 + th) * 8 + t8) * 128 + e];
            out[(size_t)(b * NT + t0 + t) * EMB + e] = s * rn;
        }
    }
}

extern "C" void kernel_launch(void* const* d_in, const int* in_sizes, int n_in,
                              void* d_out, int out_size)
{
    const float* tvecs = (const float*)d_in[0];
    const float* cvecs = (const float*)d_in[1];
    const float* W_w   = (const float*)d_in[2];
    const float* W_b   = (const float*)d_in[3];
    const float* h_w   = (const float*)d_in[4];
    const int*   ti    = (const int*)d_in[6];
    const int*   ci    = (const int*)d_in[7];
    const unsigned char* mask = (const unsigned char*)d_in[8];

    cudaFuncSetAttribute(proj_kernel, cudaFuncAttributeMaxDynamicSharedMemorySize, K1_BYTES);
    cudaFuncSetAttribute(att_kernel,  cudaFuncAttributeMaxDynamicSharedMemorySize, K2_BYTES);
    proj_kernel<<<K1_BLOCKS, 256, K1_BYTES>>>(tvecs, cvecs, W_w, W_b, ti, ci);
    att_kernel<<<B_ * 4, 256, K2_BYTES>>>(cvecs, h_w, ci, mask, (float*)d_out);
}

// round 11
// speedup vs baseline: 1.2044x; 1.0096x over previous
#include <cuda_runtime.h>

#define B_   128
#define NT   64
#define WIN  200
#define EMB  128

typedef unsigned long long ull;
#define NEG_INF (__int_as_float(0xff800000))

__device__ __forceinline__ ull fma2v(ull a, ull b, ull c) {
    ull d; asm("fma.rn.f32x2 %0, %1, %2, %3;" : "=l"(d) : "l"(a), "l"(b), "l"(c)); return d;
}
__device__ __forceinline__ ull pack2(float x, float y) {
    ull d; asm("mov.b64 %0, {%1, %2};" : "=l"(d) : "f"(x), "f"(y)); return d;
}
__device__ __forceinline__ float2 unpack2(ull a) {
    float2 r; asm("mov.b64 {%0, %1}, %2;" : "=f"(r.x), "=f"(r.y) : "l"(a)); return r;
}
__device__ __forceinline__ void relu_dot2(ull& acc, ull hp, ull hq, ull hw) {
    asm("{\n\t"
        ".reg .b64 s;\n\t"
        ".reg .f32 lo, hi;\n\t"
        "add.rn.f32x2 s, %1, %2;\n\t"
        "mov.b64 {lo, hi}, s;\n\t"
        "max.f32 lo, lo, 0f00000000;\n\t"
        "max.f32 hi, hi, 0f00000000;\n\t"
        "mov.b64 s, {lo, hi};\n\t"
        "fma.rn.f32x2 %0, s, %3, %0;\n\t"
        "}" : "+l"(acc) : "l"(hp), "l"(hq), "l"(hw));
}

// global scratch (L2-resident)
// HQT: n-chunked transposed [b][32][200][4]  -> coalesced K2 reads
__device__ float HQT[B_ * 32 * WIN * 4];
__device__ float HPg[B_ * NT * EMB];    // row-major [b*64+t][128]

// ===================== K1: projections, broadcast-X / conflict-free-W ======
// grid = 800 (hq, 32 rows) + 256 (hp); block 256 = 8 warps x 4 rows.
#define K1_HQ_BLOCKS 800
#define K1_BLOCKS    1056

#define K1_X    0               /* [32][132]; reused as transpose buffer */
#define K1_WC   4224            /* [32][130] */
#define K1_ITM  8384            /* 32 ints   */
#define K1_FLOATS 8416
#define K1_BYTES (K1_FLOATS * 4)

__global__ void __launch_bounds__(256)
proj_kernel(const float* __restrict__ tvecs, const float* __restrict__ cvecs,
            const float* __restrict__ W_w, const float* __restrict__ W_b,
            const int* __restrict__ titems, const int* __restrict__ citems)
{
    extern __shared__ float sm[];
    float* X  = sm + K1_X;
    float* Wc = sm + K1_WC;
    int*  itm = (int*)(sm + K1_ITM);
    const int tid = threadIdx.x;
    const int warp = tid >> 5, lane = tid & 31;

    const bool is_hq = blockIdx.x < K1_HQ_BLOCKS;
    const int rbase = (is_hq ? blockIdx.x : (blockIdx.x - K1_HQ_BLOCKS)) * 32;
    const float* vecs = is_hq ? cvecs : tvecs;
    const int* items  = is_hq ? citems : titems;
    const int rowsper = is_hq ? WIN : NT;
    const int wcol    = is_hq ? EMB : 0;

    if (tid < 32) {
        int r = rbase + tid;
        itm[tid] = items[(r / rowsper) * rowsper + (r % rowsper)];
    }
    __syncthreads();

    // gather X rows [32][128] (pitch 132), coalesced per row
    for (int i = tid; i < 32 * 32; i += 256) {
        int row = i >> 5, c = i & 31;
        *(float4*)(X + row * 132 + c * 4) =
            *(const float4*)(vecs + (size_t)itm[row] * EMB + c * 4);
    }

    ull acc[4][2];
#pragma unroll
    for (int r = 0; r < 4; r++) { acc[r][0] = 0ull; acc[r][1] = 0ull; }

    for (int ec = 0; ec < 4; ++ec) {
        __syncthreads();
        for (int i = tid; i < 4096; i += 256) {
            int n = i >> 5, e = i & 31;
            Wc[e * 130 + n] = W_w[n * 256 + wcol + ec * 32 + e];
        }
        __syncthreads();
#pragma unroll
        for (int e4 = 0; e4 < 8; ++e4) {
            float4 xv[4];
#pragma unroll
            for (int r = 0; r < 4; r++)   // lane-uniform -> broadcast
                xv[r] = *(const float4*)(X + (warp * 4 + r) * 132 + ec * 32 + e4 * 4);
#pragma unroll
            for (int s = 0; s < 4; ++s) {
                int e = e4 * 4 + s;
                ull wa = *(const ull*)(Wc + e * 130 + 2 * lane);        // conflict-free
                ull wb = *(const ull*)(Wc + e * 130 + 64 + 2 * lane);   // conflict-free
#pragma unroll
                for (int r = 0; r < 4; r++) {
                    float x = (s == 0) ? xv[r].x : (s == 1) ? xv[r].y
                             : (s == 2) ? xv[r].z : xv[r].w;
                    ull xd = pack2(x, x);
                    acc[r][0] = fma2v(xd, wa, acc[r][0]);
                    acc[r][1] = fma2v(xd, wb, acc[r][1]);
                }
            }
        }
    }
    __syncthreads();    // all reads of X done -> safe to overwrite

    if (is_hq) {
        // +Wb, stage into X [32 w][132 n], then coalesced transposed store
        float2 b0 = *(const float2*)(W_b + 2 * lane);
        float2 b1 = *(const float2*)(W_b + 64 + 2 * lane);
#pragma unroll
        for (int r = 0; r < 4; r++) {
            int wl = warp * 4 + r;
            float2 a0 = unpack2(acc[r][0]); a0.x += b0.x; a0.y += b0.y;
            float2 a1 = unpack2(acc[r][1]); a1.x += b1.x; a1.y += b1.y;
            *(float2*)(X + wl * 132 + 2 * lane) = a0;
            *(float2*)(X + wl * 132 + 64 + 2 * lane) = a1;
        }
        __syncthreads();
        // warp i stores chunks ns = 4i..4i+3; lane l handles global row rbase+l
        int r = rbase + lane;
        int bb = r / WIN, ww = r % WIN;
#pragma unroll
        for (int k = 0; k < 4; ++k) {
            int ns = warp * 4 + k;
            float4 v = *(const float4*)(X + lane * 132 + ns * 4);   // conflict-free
            *(float4*)(HQT + (size_t)(bb * 32 + ns) * 800 + ww * 4) = v;  // coalesced
        }
    } else {
        // hp: row-major coalesced store
#pragma unroll
        for (int r = 0; r < 4; r++) {
            int rg = rbase + warp * 4 + r;
            *(float2*)(HPg + (size_t)rg * EMB + 2 * lane) = unpack2(acc[r][0]);
            *(float2*)(HPg + (size_t)rg * EMB + 64 + 2 * lane) = unpack2(acc[r][1]);
        }
    }
}

// ===================== K2: relu-dot + softmax + AV =====================
// grid 512 = 128 b x 4 t-tiles(16); block 256 (8 warps); 4 CTAs/SM target
#define K2_SHP   0
#define K2_SCR   0
#define K2_HW    8192
#define K2_ATT   8320           /* [16][224] */
#define K2_MADD  11904
#define K2_CI    12104
#define K2_MISC  12304          /* [0]=rnorm [1]=mask flag */
#define K2_FLOATS 12312
#define K2_BYTES (K2_FLOATS * 4)

__global__ void __launch_bounds__(256, 4)
att_kernel(const float* __restrict__ cvecs, const float* __restrict__ h_w,
           const int* __restrict__ citems, const unsigned char* __restrict__ mask,
           float* __restrict__ out)
{
    extern __shared__ float sm[];
    float* SHP  = sm + K2_SHP;
    float* SHW  = sm + K2_HW;
    float* ATT  = sm + K2_ATT;
    float* MADD = sm + K2_MADD;
    int*   CI   = (int*)(sm + K2_CI);
    const int tid = threadIdx.x;
    const int b  = blockIdx.x >> 2;
    const int t0 = (blockIdx.x & 3) * 16;
    const int warp = tid >> 5, lane = tid & 31;

    if (tid == 0) ((int*)sm)[K2_MISC + 1] = 0;
    __syncthreads();
    if (tid < 200) {
        unsigned w32 = ((const unsigned*)mask)[tid];
        if (w32 > 1u) ((int*)sm)[K2_MISC + 1] = 1;   // benign race
    }
    __syncthreads();
    {
        const bool bytes_layout = ((int*)sm)[K2_MISC + 1] != 0;
        if (tid < 200) {
            int mv = bytes_layout ? (int)mask[b * WIN + tid]
                                  : ((const int*)mask)[b * WIN + tid];
            MADD[tid] = mv ? NEG_INF : 0.0f;
            CI[tid] = citems[b * WIN + tid];
        }
        if (tid < 128) SHW[tid] = h_w[tid];
    }
    for (int i = tid; i < 16 * 32; i += 256) {
        int t = i >> 5, c = i & 31;
        *(float4*)(SHP + t * 132 + c * 4) =
            *(const float4*)(HPg + ((size_t)(b * NT + t0 + t)) * EMB + c * 4);
    }
    __syncthreads();
    if (tid < 32) {  // rnorm (read at the very end)
        float c = 0.0f;
        for (int w = tid; w < WIN; w += 32) c += (MADD[w] < 0.0f) ? 1.0f : 0.0f;
#pragma unroll
        for (int o = 16; o; o >>= 1) c += __shfl_xor_sync(0xffffffffu, c, o);
        if (tid == 0) sm[K2_MISC] = 1.0f / sqrtf(1000.0f - c);
    }

    // ---- att: thread owns w; hq from HQT (coalesced); hp/hw broadcasts ----
    {
        const int w = tid;
        const bool act = (w < WIN);
        const float* hqp = HQT + (size_t)b * 25600 + (act ? w : 0) * 4;
        ull acc[16];
#pragma unroll
        for (int t = 0; t < 16; ++t) acc[t] = 0ull;
#pragma unroll 2
        for (int ns = 0; ns < 32; ++ns) {
            ulonglong2 hq = *(const ulonglong2*)(hqp + ns * 800);   // lanes 16B apart
            ulonglong2 hw = *(const ulonglong2*)(SHW + ns * 4);
#pragma unroll
            for (int t = 0; t < 16; ++t) {
                ulonglong2 p = *(const ulonglong2*)(SHP + t * 132 + ns * 4);
                relu_dot2(acc[t], p.x, hq.x, hw.x);
                relu_dot2(acc[t], p.y, hq.y, hw.y);
            }
        }
        if (act) {
#pragma unroll
            for (int t = 0; t < 16; ++t) {
                float2 a = unpack2(acc[t]);
                ATT[t * 224 + w] = a.x + a.y;
            }
        }
    }
    __syncthreads();

    // ---- softmax over w per t (8 warps x 2t) ----
    for (int t = warp; t < 16; t += 8) {
        float v[7], p[7];
        float m = NEG_INF;
#pragma unroll
        for (int k = 0; k < 7; k++) {
            int w = lane + 32 * k;
            v[k] = (w < WIN) ? (ATT[t * 224 + w] + MADD[w]) : NEG_INF;
            m = fmaxf(m, v[k]);
        }
#pragma unroll
        for (int o = 16; o; o >>= 1) m = fmaxf(m, __shfl_xor_sync(0xffffffffu, m, o));
        float s = 0.0f;
#pragma unroll
        for (int k = 0; k < 7; k++) { p[k] = __expf(v[k] - m); s += p[k]; }
#pragma unroll
        for (int o = 16; o; o >>= 1) s += __shfl_xor_sync(0xffffffffu, s, o);
        float inv = 1.0f / s;
#pragma unroll
        for (int k = 0; k < 7; k++) {
            int w = lane + 32 * k;
            if (w < WIN) ATT[t * 224 + w] = p[k] * inv;
        }
    }
    __syncthreads();   // ATT final; SHP dead -> scratch reuse safe

    // ---- AV: warp = (t-half, w-quarter); kv from L2; partials in smem ----
    {
        const int th = warp & 1, wg = warp >> 1;
        float* SCR = sm + K2_SCR;
        ull acc[8][2];
#pragma unroll
        for (int t8 = 0; t8 < 8; ++t8) { acc[t8][0] = 0ull; acc[t8][1] = 0ull; }
#pragma unroll 2
        for (int wi = 0; wi < 50; ++wi) {
            int w = wg * 50 + wi;
            ulonglong2 kv = *(const ulonglong2*)(cvecs + (size_t)CI[w] * EMB + lane * 4);
#pragma unroll
            for (int t8 = 0; t8 < 8; ++t8) {
                float x = ATT[(th * 8 + t8) * 224 + w];   // broadcast
                ull d = pack2(x, x);
                acc[t8][0] = fma2v(d, kv.x, acc[t8][0]);
                acc[t8][1] = fma2v(d, kv.y, acc[t8][1]);
            }
        }
#pragma unroll
        for (int t8 = 0; t8 < 8; ++t8) {
            ulonglong2 v; v.x = acc[t8][0]; v.y = acc[t8][1];
            *(ulonglong2*)(SCR + (size_t)(warp * 8 + t8) * 128 + lane * 4) = v;
        }
    }
    __syncthreads();

    // ---- reduce 4 partials + scale + store ----
    {
        const float rn = sm[K2_MISC];
        for (int i = tid; i < 16 * 128; i += 256) {
            int t = i >> 7, e = i & 127;
            int th = t >> 3, t8 = t & 7;
            float s = 0.0f;
#pragma unroll
            for (int wg = 0; wg < 4; ++wg)
                s += sm[K2_SCR + (size_t)((wg * 2 + th) * 8 + t8) * 128 + e];
            out[(size_t)(b * NT + t0 + t) * EMB + e] = s * rn;
        }
    }
}

extern "C" void kernel_launch(void* const* d_in, const int* in_sizes, int n_in,
                              void* d_out, int out_size)
{
    const float* tvecs = (const float*)d_in[0];
    const float* cvecs = (const float*)d_in[1];
    const float* W_w   = (const float*)d_in[2];
    const float* W_b   = (const float*)d_in[3];
    const float* h_w   = (const float*)d_in[4];
    const int*   ti    = (const int*)d_in[6];
    const int*   ci    = (const int*)d_in[7];
    const unsigned char* mask = (const unsigned char*)d_in[8];

    cudaFuncSetAttribute(proj_kernel, cudaFuncAttributeMaxDynamicSharedMemorySize, K1_BYTES);
    cudaFuncSetAttribute(att_kernel,  cudaFuncAttributeMaxDynamicSharedMemorySize, K2_BYTES);
    proj_kernel<<<K1_BLOCKS, 256, K1_BYTES>>>(tvecs, cvecs, W_w, W_b, ti, ci);
    att_kernel<<<B_ * 4, 256, K2_BYTES>>>(cvecs, h_w, ci, mask, (float*)d_out);
}

// round 12
// speedup vs baseline: 1.2259x; 1.0179x over previous
#include <cuda_runtime.h>

#define B_   128
#define NT   64
#define WIN  200
#define EMB  128

typedef unsigned long long ull;
#define NEG_INF (__int_as_float(0xff800000))

__device__ __forceinline__ ull fma2v(ull a, ull b, ull c) {
    ull d; asm("fma.rn.f32x2 %0, %1, %2, %3;" : "=l"(d) : "l"(a), "l"(b), "l"(c)); return d;
}
__device__ __forceinline__ ull pack2(float x, float y) {
    ull d; asm("mov.b64 %0, {%1, %2};" : "=l"(d) : "f"(x), "f"(y)); return d;
}
__device__ __forceinline__ float2 unpack2(ull a) {
    float2 r; asm("mov.b64 {%0, %1}, %2;" : "=f"(r.x), "=f"(r.y) : "l"(a)); return r;
}
__device__ __forceinline__ void relu_dot2(ull& acc, ull hp, ull hq, ull hw) {
    asm("{\n\t"
        ".reg .b64 s;\n\t"
        ".reg .f32 lo, hi;\n\t"
        "add.rn.f32x2 s, %1, %2;\n\t"
        "mov.b64 {lo, hi}, s;\n\t"
        "max.f32 lo, lo, 0f00000000;\n\t"
        "max.f32 hi, hi, 0f00000000;\n\t"
        "mov.b64 s, {lo, hi};\n\t"
        "fma.rn.f32x2 %0, s, %3, %0;\n\t"
        "}" : "+l"(acc) : "l"(hp), "l"(hq), "l"(hw));
}

// global scratch (L2-resident)
__device__ float HQT[B_ * 32 * WIN * 4];   // n-chunked [b][32][200][4]
__device__ float HPg[B_ * NT * EMB];       // row-major [b*64+t][128]

// ===================== K1: projections (unchanged from R11) ================
#define K1_HQ_BLOCKS 800
#define K1_BLOCKS    1056

#define K1_X    0               /* [32][132]; reused as transpose buffer */
#define K1_WC   4224            /* [32][130] */
#define K1_ITM  8384            /* 32 ints   */
#define K1_FLOATS 8416
#define K1_BYTES (K1_FLOATS * 4)

__global__ void __launch_bounds__(256)
proj_kernel(const float* __restrict__ tvecs, const float* __restrict__ cvecs,
            const float* __restrict__ W_w, const float* __restrict__ W_b,
            const int* __restrict__ titems, const int* __restrict__ citems)
{
    extern __shared__ float sm[];
    float* X  = sm + K1_X;
    float* Wc = sm + K1_WC;
    int*  itm = (int*)(sm + K1_ITM);
    const int tid = threadIdx.x;
    const int warp = tid >> 5, lane = tid & 31;

    const bool is_hq = blockIdx.x < K1_HQ_BLOCKS;
    const int rbase = (is_hq ? blockIdx.x : (blockIdx.x - K1_HQ_BLOCKS)) * 32;
    const float* vecs = is_hq ? cvecs : tvecs;
    const int* items  = is_hq ? citems : titems;
    const int rowsper = is_hq ? WIN : NT;
    const int wcol    = is_hq ? EMB : 0;

    if (tid < 32) {
        int r = rbase + tid;
        itm[tid] = items[(r / rowsper) * rowsper + (r % rowsper)];
    }
    __syncthreads();

    for (int i = tid; i < 32 * 32; i += 256) {
        int row = i >> 5, c = i & 31;
        *(float4*)(X + row * 132 + c * 4) =
            *(const float4*)(vecs + (size_t)itm[row] * EMB + c * 4);
    }

    ull acc[4][2];
#pragma unroll
    for (int r = 0; r < 4; r++) { acc[r][0] = 0ull; acc[r][1] = 0ull; }

    for (int ec = 0; ec < 4; ++ec) {
        __syncthreads();
        for (int i = tid; i < 4096; i += 256) {
            int n = i >> 5, e = i & 31;
            Wc[e * 130 + n] = W_w[n * 256 + wcol + ec * 32 + e];
        }
        __syncthreads();
#pragma unroll
        for (int e4 = 0; e4 < 8; ++e4) {
            float4 xv[4];
#pragma unroll
            for (int r = 0; r < 4; r++)
                xv[r] = *(const float4*)(X + (warp * 4 + r) * 132 + ec * 32 + e4 * 4);
#pragma unroll
            for (int s = 0; s < 4; ++s) {
                int e = e4 * 4 + s;
                ull wa = *(const ull*)(Wc + e * 130 + 2 * lane);
                ull wb = *(const ull*)(Wc + e * 130 + 64 + 2 * lane);
#pragma unroll
                for (int r = 0; r < 4; r++) {
                    float x = (s == 0) ? xv[r].x : (s == 1) ? xv[r].y
                             : (s == 2) ? xv[r].z : xv[r].w;
                    ull xd = pack2(x, x);
                    acc[r][0] = fma2v(xd, wa, acc[r][0]);
                    acc[r][1] = fma2v(xd, wb, acc[r][1]);
                }
            }
        }
    }
    __syncthreads();

    if (is_hq) {
        float2 b0 = *(const float2*)(W_b + 2 * lane);
        float2 b1 = *(const float2*)(W_b + 64 + 2 * lane);
#pragma unroll
        for (int r = 0; r < 4; r++) {
            int wl = warp * 4 + r;
            float2 a0 = unpack2(acc[r][0]); a0.x += b0.x; a0.y += b0.y;
            float2 a1 = unpack2(acc[r][1]); a1.x += b1.x; a1.y += b1.y;
            *(float2*)(X + wl * 132 + 2 * lane) = a0;
            *(float2*)(X + wl * 132 + 64 + 2 * lane) = a1;
        }
        __syncthreads();
        int r = rbase + lane;
        int bb = r / WIN, ww = r % WIN;
#pragma unroll
        for (int k = 0; k < 4; ++k) {
            int ns = warp * 4 + k;
            float4 v = *(const float4*)(X + lane * 132 + ns * 4);
            *(float4*)(HQT + (size_t)(bb * 32 + ns) * 800 + ww * 4) = v;
        }
    } else {
#pragma unroll
        for (int r = 0; r < 4; r++) {
            int rg = rbase + warp * 4 + r;
            *(float2*)(HPg + (size_t)rg * EMB + 2 * lane) = unpack2(acc[r][0]);
            *(float2*)(HPg + (size_t)rg * EMB + 64 + 2 * lane) = unpack2(acc[r][1]);
        }
    }
}

// ===================== K2: relu-dot + softmax + AV =====================
// grid 512 = 128 b x 4 t-tiles(16); block 256 (8 warps); 4 CTAs/SM
#define K2_SHP   0
#define K2_SCR   0
#define K2_HW    8192
#define K2_ATT   8320           /* [16][224] */
#define K2_MADD  11904
#define K2_CI    12104
#define K2_MISC  12304          /* [0]=rnorm [1]=mask flag */
#define K2_FLOATS 12312
#define K2_BYTES (K2_FLOATS * 4)

__global__ void __launch_bounds__(256, 4)
att_kernel(const float* __restrict__ cvecs, const float* __restrict__ h_w,
           const int* __restrict__ citems, const unsigned char* __restrict__ mask,
           float* __restrict__ out)
{
    extern __shared__ float sm[];
    float* SHP  = sm + K2_SHP;
    float* SHW  = sm + K2_HW;
    float* ATT  = sm + K2_ATT;
    float* MADD = sm + K2_MADD;
    int*   CI   = (int*)(sm + K2_CI);
    const int tid = threadIdx.x;
    const int b  = blockIdx.x >> 2;
    const int t0 = (blockIdx.x & 3) * 16;
    const int warp = tid >> 5, lane = tid & 31;

    if (tid == 0) ((int*)sm)[K2_MISC + 1] = 0;
    __syncthreads();
    if (tid < 200) {
        unsigned w32 = ((const unsigned*)mask)[tid];
        if (w32 > 1u) ((int*)sm)[K2_MISC + 1] = 1;   // benign race
    }
    __syncthreads();
    {
        const bool bytes_layout = ((int*)sm)[K2_MISC + 1] != 0;
        if (tid < 200) {
            int mv = bytes_layout ? (int)mask[b * WIN + tid]
                                  : ((const int*)mask)[b * WIN + tid];
            MADD[tid] = mv ? NEG_INF : 0.0f;
            CI[tid] = citems[b * WIN + tid];
        }
        if (tid < 128) SHW[tid] = h_w[tid];
    }
    for (int i = tid; i < 16 * 32; i += 256) {
        int t = i >> 5, c = i & 31;
        *(float4*)(SHP + t * 132 + c * 4) =
            *(const float4*)(HPg + ((size_t)(b * NT + t0 + t)) * EMB + c * 4);
    }
    __syncthreads();
    if (tid < 32) {  // rnorm
        float c = 0.0f;
        for (int w = tid; w < WIN; w += 32) c += (MADD[w] < 0.0f) ? 1.0f : 0.0f;
#pragma unroll
        for (int o = 16; o; o >>= 1) c += __shfl_xor_sync(0xffffffffu, c, o);
        if (tid == 0) sm[K2_MISC] = 1.0f / sqrtf(1000.0f - c);
    }

    // ---- att: thread owns w; TWO passes of 8 t (low reg pressure) ----
    {
        const int w = tid;
        const bool act = (w < WIN);
        const float* hqp = HQT + (size_t)b * 25600 + (act ? w : 0) * 4;
#pragma unroll
        for (int th = 0; th < 2; ++th) {
            const float* shp = SHP + th * 8 * 132;
            ull acc[8];
#pragma unroll
            for (int t = 0; t < 8; ++t) acc[t] = 0ull;
#pragma unroll 2
            for (int ns = 0; ns < 32; ++ns) {
                ulonglong2 hq = *(const ulonglong2*)(hqp + ns * 800);
                ulonglong2 hw = *(const ulonglong2*)(SHW + ns * 4);
#pragma unroll
                for (int t = 0; t < 8; ++t) {
                    ulonglong2 p = *(const ulonglong2*)(shp + t * 132 + ns * 4);
                    relu_dot2(acc[t], p.x, hq.x, hw.x);
                    relu_dot2(acc[t], p.y, hq.y, hw.y);
                }
            }
            if (act) {
#pragma unroll
                for (int t = 0; t < 8; ++t) {
                    float2 a = unpack2(acc[t]);
                    ATT[(th * 8 + t) * 224 + w] = a.x + a.y;
                }
            }
        }
    }
    __syncthreads();

    // ---- softmax over w per t (8 warps x 2t) ----
    for (int t = warp; t < 16; t += 8) {
        float v[7], p[7];
        float m = NEG_INF;
#pragma unroll
        for (int k = 0; k < 7; k++) {
            int w = lane + 32 * k;
            v[k] = (w < WIN) ? (ATT[t * 224 + w] + MADD[w]) : NEG_INF;
            m = fmaxf(m, v[k]);
        }
#pragma unroll
        for (int o = 16; o; o >>= 1) m = fmaxf(m, __shfl_xor_sync(0xffffffffu, m, o));
        float s = 0.0f;
#pragma unroll
        for (int k = 0; k < 7; k++) { p[k] = __expf(v[k] - m); s += p[k]; }
#pragma unroll
        for (int o = 16; o; o >>= 1) s += __shfl_xor_sync(0xffffffffu, s, o);
        float inv = 1.0f / s;
#pragma unroll
        for (int k = 0; k < 7; k++) {
            int w = lane + 32 * k;
            if (w < WIN) ATT[t * 224 + w] = p[k] * inv;
        }
    }
    __syncthreads();   // ATT final; SHP dead -> scratch reuse safe

    // ---- AV: warp = (t-half, w-quarter); kv from L2; partials in smem ----
    {
        const int th = warp & 1, wg = warp >> 1;
        float* SCR = sm + K2_SCR;
        ull acc[8][2];
#pragma unroll
        for (int t8 = 0; t8 < 8; ++t8) { acc[t8][0] = 0ull; acc[t8][1] = 0ull; }
#pragma unroll 2
        for (int wi = 0; wi < 50; ++wi) {
            int w = wg * 50 + wi;
            ulonglong2 kv = *(const ulonglong2*)(cvecs + (size_t)CI[w] * EMB + lane * 4);
#pragma unroll
            for (int t8 = 0; t8 < 8; ++t8) {
                float x = ATT[(th * 8 + t8) * 224 + w];   // broadcast
                ull d = pack2(x, x);
                acc[t8][0] = fma2v(d, kv.x, acc[t8][0]);
                acc[t8][1] = fma2v(d, kv.y, acc[t8][1]);
            }
        }
#pragma unroll
        for (int t8 = 0; t8 < 8; ++t8) {
            ulonglong2 v; v.x = acc[t8][0]; v.y = acc[t8][1];
            *(ulonglong2*)(SCR + (size_t)(warp * 8 + t8) * 128 + lane * 4) = v;
        }
    }
    __syncthreads();

    // ---- reduce 4 partials + scale + store ----
    {
        const float rn = sm[K2_MISC];
        for (int i = tid; i < 16 * 128; i += 256) {
            int t = i >> 7, e = i & 127;
            int th = t >> 3, t8 = t & 7;
            float s = 0.0f;
#pragma unroll
            for (int wg = 0; wg < 4; ++wg)
                s += sm[K2_SCR + (size_t)((wg * 2 + th) * 8 + t8) * 128 + e];
            out[(size_t)(b * NT + t0 + t) * EMB + e] = s * rn;
        }
    }
}

extern "C" void kernel_launch(void* const* d_in, const int* in_sizes, int n_in,
                              void* d_out, int out_size)
{
    const float* tvecs = (const float*)d_in[0];
    const float* cvecs = (const float*)d_in[1];
    const float* W_w   = (const float*)d_in[2];
    const float* W_b   = (const float*)d_in[3];
    const float* h_w   = (const float*)d_in[4];
    const int*   ti    = (const int*)d_in[6];
    const int*   ci    = (const int*)d_in[7];
    const unsigned char* mask = (const unsigned char*)d_in[8];

    cudaFuncSetAttribute(proj_kernel, cudaFuncAttributeMaxDynamicSharedMemorySize, K1_BYTES);
    cudaFuncSetAttribute(att_kernel,  cudaFuncAttributeMaxDynamicSharedMemorySize, K2_BYTES);
    proj_kernel<<<K1_BLOCKS, 256, K1_BYTES>>>(tvecs, cvecs, W_w, W_b, ti, ci);
    att_kernel<<<B_ * 4, 256, K2_BYTES>>>(cvecs, h_w, ci, mask, (float*)d_out);
}